// round 16
// baseline (speedup 1.0000x reference)
#include <cuda_runtime.h>
#include <cuda_bf16.h>
#include <math.h>
#include <stdint.h>

#define DEPTH  8
#define DDIM   1024
#define DI     2048
#define NSTATE 16
#define DCONV  4
#define DTRANK 64
#define BB     2
#define LLEN   2048
#define ROWS   (BB*LLEN)           // 4096
#define XZW    (2*DI)              // 4096
#define XDBLW  (DTRANK + 2*NSTATE) // 96

// ---------------- scratch (static device globals; no allocation) ----------
__device__ float g_xz   [(size_t)ROWS * XZW];
__device__ float g_xs   [(size_t)ROWS * DI];
__device__ float g_xdbl [(size_t)ROWS * XDBLW];
__device__ float g_delta[(size_t)ROWS * DI];
__device__ __nv_bfloat16 g_sa  [(size_t)ROWS * 2 * DI];        // shared A-split buffer
__device__ __nv_bfloat16 g_sdt [(size_t)ROWS * 2 * DTRANK];    // dt split (from x_proj epi)
__device__ __nv_bfloat16 g_swi [(size_t)DEPTH * XZW * 2 * DDIM];   // Wi split
__device__ __nv_bfloat16 g_swx [(size_t)DEPTH * 128 * 2 * DI];     // Wx split (rows padded 128)
__device__ __nv_bfloat16 g_swdt[(size_t)DEPTH * DI * 2 * DTRANK];  // Wdt split
__device__ __nv_bfloat16 g_swo [(size_t)DEPTH * DDIM * 2 * DI];    // Wo split

// ======================= helpers ==========================================
__device__ __forceinline__ uint32_t s2u(const void* p) {
    uint32_t a;
    asm("{ .reg .u64 t; cvta.to.shared.u64 t, %1; cvt.u32.u64 %0, t; }"
        : "=r"(a) : "l"(p));
    return a;
}
#define CP16(dst, src) \
    asm volatile("cp.async.cg.shared.global [%0], [%1], 16;" :: "r"(dst), "l"(src))
#define CP_COMMIT()  asm volatile("cp.async.commit_group;" ::: "memory")
#define CP_WAIT0()   asm volatile("cp.async.wait_group 0;" ::: "memory")

__device__ __forceinline__ void mma16816(float* c, uint32_t a0, uint32_t a1,
                                         uint32_t a2, uint32_t a3,
                                         uint32_t b0, uint32_t b1) {
    asm volatile(
        "mma.sync.aligned.m16n8k16.row.col.f32.bf16.bf16.f32 "
        "{%0,%1,%2,%3}, {%4,%5,%6,%7}, {%8,%9}, {%0,%1,%2,%3};"
        : "+f"(c[0]), "+f"(c[1]), "+f"(c[2]), "+f"(c[3])
        : "r"(a0), "r"(a1), "r"(a2), "r"(a3), "r"(b0), "r"(b1));
}
__device__ __forceinline__ void bf16_split(float x, __nv_bfloat16& h, __nv_bfloat16& l) {
    h = __float2bfloat16(x);
    l = __float2bfloat16(x - __bfloat162float(h));
}

// ======================= standalone bf16 2-way split ======================
// out[r, 0:K)=h, [K:2K)=l; rows >= R zeroed.
__global__ __launch_bounds__(256) void split2_kernel(
    const float* __restrict__ X, int R, int Rpad, int K, int ldx,
    __nv_bfloat16* __restrict__ out)
{
    long i = (long)blockIdx.x * blockDim.x + threadIdx.x;
    if (i >= (long)Rpad * K) return;
    int k = (int)(i % K);
    long r = i / K;
    float x = (r < R) ? X[r * (long)ldx + k] : 0.f;
    __nv_bfloat16 h, l; bf16_split(x, h, l);
    __nv_bfloat16* o = out + r * (long)(2 * K);
    o[k] = h; o[K + k] = l;
}

// ======================= bf16 GEMM, 3 segments, chunk-spill ===============
// C[M,N] = {hh + lh + hl} of A_seg[M,K] * W_seg[N,K]^T; A,W: [rows, 2K]=[h|l].
// CTA tile TM x 128 (TM=128: warps 2x4, 64x32 each; TM=32: warps 1x8, 32x16).
// BK=32; each chunk's 2-step mma chain spilled into exact fp32 regs (R14/15).
#define BKC   32
#define SSTR  40
#define SEGA_PACK 0x010u   // A segments per pass: 0,1,0
#define SEGB_PACK 0x100u   // B segments per pass: 0,0,1

template<int TM, int WGM, int MT, int NT>
__global__ __launch_bounds__(256) void bf16_gemm_kernel(
    const __nv_bfloat16* __restrict__ A,
    const __nv_bfloat16* __restrict__ W,
    float* __restrict__ C, int ldc,
    int Ntrue, int K,
    int do_sp, const float* __restrict__ bias,
    __nv_bfloat16* __restrict__ sdt_out)   // if non-null: emit split of cols<64
{
    constexpr int WGN = 8 / WGM;
    constexpr int WARP_M = TM / WGM;
    constexpr int WARP_N = 128 / WGN;

    __shared__ __nv_bfloat16 sA[2][TM * SSTR];
    __shared__ __nv_bfloat16 sB[2][128 * SSTR];

    const int tid = threadIdx.x;
    const int m0 = blockIdx.y * TM;
    const int n0 = blockIdx.x * 128;

    // ---- loaders ---------------------------------------------------------
    const int ldrowB = tid >> 1, ldoffB = (tid & 1) * 32;
    const char* gB = (const char*)(W + (size_t)(n0 + ldrowB) * (2 * K)) + ldoffB;
    const uint32_t dB[2] = { s2u(&sB[0][0]) + ldrowB * (SSTR * 2) + ldoffB,
                             s2u(&sB[1][0]) + ldrowB * (SSTR * 2) + ldoffB };
    int ldrowA, ldoffA;
    if (TM == 128) { ldrowA = tid >> 1; ldoffA = (tid & 1) * 32; }
    else           { ldrowA = tid >> 2; ldoffA = (tid & 3) * 16; }
    const char* gA = (const char*)(A + (size_t)(m0 + ldrowA) * (2 * K)) + ldoffA;
    const uint32_t dA[2] = { s2u(&sA[0][0]) + ldrowA * (SSTR * 2) + ldoffA,
                             s2u(&sA[1][0]) + ldrowA * (SSTR * 2) + ldoffA };

    const int nkr = K / BKC;
    const int total = 3 * nkr;

    auto load_chunk = [&](int c, int buf) {
        const int p = c / nkr;
        const int kk = c - p * nkr;
        const int sa_off = (int)((SEGA_PACK >> (4 * p)) & 3) * K + kk * BKC;
        const int sb_off = (int)((SEGB_PACK >> (4 * p)) & 3) * K + kk * BKC;
        const char* pb = gB + (size_t)sb_off * 2;
        CP16(dB[buf],      pb);
        CP16(dB[buf] + 16, pb + 16);
        const char* pa = gA + (size_t)sa_off * 2;
        if (TM == 128) {
            CP16(dA[buf],      pa);
            CP16(dA[buf] + 16, pa + 16);
        } else if (tid < TM * 4) {
            CP16(dA[buf], pa);
        }
    };

    // ---- warp/lane decomposition ----------------------------------------
    const int wid = tid >> 5, lane = tid & 31;
    const int wm = (WGM == 1) ? 0 : (wid & (WGM - 1));
    const int wn = wid / WGM;
    const int g = lane >> 2, t = lane & 3;

    float accP[MT][NT][4];
    float acc[MT][NT][4];
#pragma unroll
    for (int i = 0; i < MT; i++)
#pragma unroll
        for (int j = 0; j < NT; j++)
#pragma unroll
            for (int q = 0; q < 4; q++) { accP[i][j][q] = 0.f; acc[i][j][q] = 0.f; }

    load_chunk(0, 0);
    CP_COMMIT();

    for (int c = 0; c < total; c++) {
        const int buf = c & 1;
        CP_WAIT0();
        __syncthreads();
        if (c + 1 < total) {
            load_chunk(c + 1, buf ^ 1);
            CP_COMMIT();
        }

        const __nv_bfloat16* pA = &sA[buf][0];
        const __nv_bfloat16* pB = &sB[buf][0];
#pragma unroll
        for (int ks = 0; ks < 2; ks++) {
            const int kb = ks * 16 + t * 2;
            uint32_t af[MT][4], bf[NT][2];
#pragma unroll
            for (int mt = 0; mt < MT; mt++) {
                const int r = wm * WARP_M + mt * 16 + g;
                af[mt][0] = *(const uint32_t*)&pA[r * SSTR + kb];
                af[mt][1] = *(const uint32_t*)&pA[(r + 8) * SSTR + kb];
                af[mt][2] = *(const uint32_t*)&pA[r * SSTR + kb + 8];
                af[mt][3] = *(const uint32_t*)&pA[(r + 8) * SSTR + kb + 8];
            }
#pragma unroll
            for (int nt = 0; nt < NT; nt++) {
                const int cc = wn * WARP_N + nt * 8 + g;
                bf[nt][0] = *(const uint32_t*)&pB[cc * SSTR + kb];
                bf[nt][1] = *(const uint32_t*)&pB[cc * SSTR + kb + 8];
            }
#pragma unroll
            for (int mt = 0; mt < MT; mt++)
#pragma unroll
                for (int nt = 0; nt < NT; nt++)
                    mma16816(acc[mt][nt], af[mt][0], af[mt][1], af[mt][2],
                             af[mt][3], bf[nt][0], bf[nt][1]);
        }
#pragma unroll
        for (int mt = 0; mt < MT; mt++)
#pragma unroll
            for (int nt = 0; nt < NT; nt++)
#pragma unroll
                for (int q = 0; q < 4; q++) {
                    accP[mt][nt][q] += acc[mt][nt][q];
                    acc[mt][nt][q] = 0.f;
                }
    }

    // ---- epilogue --------------------------------------------------------
#pragma unroll
    for (int mt = 0; mt < MT; mt++) {
        const int r0 = m0 + wm * WARP_M + mt * 16 + g;
#pragma unroll
        for (int nt = 0; nt < NT; nt++) {
            const int cc = n0 + wn * WARP_N + nt * 8 + t * 2;
            if (cc >= Ntrue) continue;
            float v0 = accP[mt][nt][0], v1 = accP[mt][nt][1];
            float v2 = accP[mt][nt][2], v3 = accP[mt][nt][3];
            if (do_sp) {
                const float b0 = bias[cc], b1 = bias[cc + 1];
                v0 += b0; v1 += b1; v2 += b0; v3 += b1;
                v0 = fmaxf(v0, 0.f) + log1pf(expf(-fabsf(v0)));
                v1 = fmaxf(v1, 0.f) + log1pf(expf(-fabsf(v1)));
                v2 = fmaxf(v2, 0.f) + log1pf(expf(-fabsf(v2)));
                v3 = fmaxf(v3, 0.f) + log1pf(expf(-fabsf(v3)));
            }
            *(float2*)(C + (size_t)r0 * ldc + cc)       = make_float2(v0, v1);
            *(float2*)(C + (size_t)(r0 + 8) * ldc + cc) = make_float2(v2, v3);
            if (sdt_out != nullptr && cc < DTRANK) {
                __nv_bfloat16 h, l;
                __nv_bfloat16* o0 = sdt_out + (size_t)r0 * (2 * DTRANK);
                __nv_bfloat16* o1 = sdt_out + (size_t)(r0 + 8) * (2 * DTRANK);
                bf16_split(v0, h, l); o0[cc] = h;     o0[DTRANK + cc] = l;
                bf16_split(v1, h, l); o0[cc + 1] = h; o0[DTRANK + cc + 1] = l;
                bf16_split(v2, h, l); o1[cc] = h;     o1[DTRANK + cc] = l;
                bf16_split(v3, h, l); o1[cc + 1] = h; o1[DTRANK + cc + 1] = l;
            }
        }
    }
}

// ---------- depthwise causal conv + bias + silu; emits fp32 + split -------
__global__ __launch_bounds__(256) void conv_silu_kernel(
    const float* __restrict__ xz, const float* __restrict__ cw,
    const float* __restrict__ cb, float* __restrict__ xs,
    __nv_bfloat16* __restrict__ xs_split)
{
    const int i = blockIdx.x * blockDim.x + threadIdx.x;
    if (i >= ROWS * DI) return;
    const int d = i & (DI - 1);
    const int r = i >> 11;
    const int t = r & (LLEN - 1);
    float acc = cb[d];
    const float* base = xz + (size_t)r * XZW + d;
#pragma unroll
    for (int j = 0; j < DCONV; j++) {
        const int tt = t - (DCONV - 1) + j;
        if (tt >= 0)
            acc += cw[d * DCONV + j] * base[(long)(tt - t) * XZW];
    }
    const float v = acc / (1.f + __expf(-acc));
    xs[i] = v;
    __nv_bfloat16 h, l; bf16_split(v, h, l);
    __nv_bfloat16* o = xs_split + (size_t)r * (2 * DI);
    o[d] = h; o[DI + d] = l;
}

// ---------- selective scan + D skip + gate, emits bf16 split of y ---------
__global__ __launch_bounds__(128) void scan_kernel(
    const float* __restrict__ xs, const float* __restrict__ delta,
    const float* __restrict__ xdbl, const float* __restrict__ A_log,
    const float* __restrict__ Dp, const float* __restrict__ xz,
    __nv_bfloat16* __restrict__ ysplit)
{
    const int lane = threadIdx.x & 15;
    const int ch = blockIdx.x * (blockDim.x >> 4) + (threadIdx.x >> 4);
    const int b = ch / DI, d = ch & (DI - 1);
    const float A  = -expf(A_log[d * NSTATE + lane]);
    const float Dd = Dp[d];

    const float* xsP = xs    + (size_t)b * LLEN * DI + d;
    const float* dlP = delta + (size_t)b * LLEN * DI + d;
    const float* bcP = xdbl  + (size_t)b * LLEN * XDBLW + DTRANK + lane;
    const float* zP  = xz    + (size_t)b * LLEN * XZW + DI + d;
    __nv_bfloat16* yP = ysplit + (size_t)b * LLEN * (2 * DI) + d;

    float h = 0.f;
    for (int t = 0; t < LLEN; t++) {
        const float dt = dlP[0];
        const float xt = xsP[0];
        const float Bt = bcP[0];
        const float Ct = bcP[NSTATE];
        const float dA = __expf(dt * A);
        h = dA * h + (dt * xt) * Bt;
        float p = h * Ct;
        p += __shfl_xor_sync(0xffffffffu, p, 1);
        p += __shfl_xor_sync(0xffffffffu, p, 2);
        p += __shfl_xor_sync(0xffffffffu, p, 4);
        p += __shfl_xor_sync(0xffffffffu, p, 8);
        if (lane == 0) {
            const float z = zP[0];
            const float v = (p + Dd * xt) * (z / (1.f + __expf(-z)));
            __nv_bfloat16 hh, ll; bf16_split(v, hh, ll);
            yP[0] = hh; yP[DI] = ll;
        }
        xsP += DI; dlP += DI; bcP += XDBLW; zP += XZW; yP += 2 * DI;
    }
}

// ---------- rmsnorm: emits fp32 (final layer) OR bf16 split (mid) ---------
__global__ __launch_bounds__(256) void rmsnorm_kernel(
    const float* __restrict__ in, const float* __restrict__ w,
    float* __restrict__ out_f32, __nv_bfloat16* __restrict__ out_split)
{
    const int r = blockIdx.x;
    const int tid = threadIdx.x;
    const float* row = in + (size_t)r * DDIM;
    float v[4];
    float ss = 0.f;
#pragma unroll
    for (int j = 0; j < 4; j++) {
        v[j] = row[tid + j * 256];
        ss += v[j] * v[j];
    }
#pragma unroll
    for (int o = 16; o > 0; o >>= 1) ss += __shfl_xor_sync(0xffffffffu, ss, o);
    __shared__ float ws[8];
    if ((tid & 31) == 0) ws[tid >> 5] = ss;
    __syncthreads();
    float tot = 0.f;
#pragma unroll
    for (int k = 0; k < 8; k++) tot += ws[k];
    const float inv = rsqrtf(tot * (1.f / (float)DDIM) + 1e-5f);
#pragma unroll
    for (int j = 0; j < 4; j++) {
        const int c = tid + j * 256;
        const float val = v[j] * inv * w[c];
        if (out_split) {
            __nv_bfloat16 h, l; bf16_split(val, h, l);
            __nv_bfloat16* o = out_split + (size_t)r * (2 * DDIM);
            o[c] = h; o[DDIM + c] = l;
        } else {
            out_f32[(size_t)r * DDIM + c] = val;
        }
    }
}

// ---------------- host launch ---------------------------------------------
static inline int cdiv(long a, int b) { return (int)((a + b - 1) / b); }

extern "C" void kernel_launch(void* const* d_in, const int* in_sizes, int n_in,
                              void* d_out, int out_size)
{
    const float* x0   = (const float*)d_in[0];
    const float* Wi   = (const float*)d_in[1];   // [8, 4096, 1024]
    const float* cw   = (const float*)d_in[2];   // [8, 2048, 4]
    const float* cb   = (const float*)d_in[3];   // [8, 2048]
    const float* Wx   = (const float*)d_in[4];   // [8, 96, 2048]
    const float* Wdt  = (const float*)d_in[5];   // [8, 2048, 64]
    const float* bdt  = (const float*)d_in[6];   // [8, 2048]
    const float* Alog = (const float*)d_in[7];   // [8, 2048, 16]
    const float* Dp   = (const float*)d_in[8];   // [8, 2048]
    const float* Wo   = (const float*)d_in[9];   // [8, 1024, 2048]
    const float* rw   = (const float*)d_in[10];  // [8, 1024]

    float *xz, *xs, *xdbl, *delta;
    __nv_bfloat16 *sa, *sdt, *swi, *swx, *swdt, *swo;
    cudaGetSymbolAddress((void**)&xz,    g_xz);
    cudaGetSymbolAddress((void**)&xs,    g_xs);
    cudaGetSymbolAddress((void**)&xdbl,  g_xdbl);
    cudaGetSymbolAddress((void**)&delta, g_delta);
    cudaGetSymbolAddress((void**)&sa,    g_sa);
    cudaGetSymbolAddress((void**)&sdt,   g_sdt);
    cudaGetSymbolAddress((void**)&swi,   g_swi);
    cudaGetSymbolAddress((void**)&swx,   g_swx);
    cudaGetSymbolAddress((void**)&swdt,  g_swdt);
    cudaGetSymbolAddress((void**)&swo,   g_swo);

    // ---- batch all weight splits up-front --------------------------------
    split2_kernel<<<cdiv((long)DEPTH * XZW * DDIM, 256), 256>>>(
        Wi, DEPTH * XZW, DEPTH * XZW, DDIM, DDIM, swi);
    for (int l = 0; l < DEPTH; l++)
        split2_kernel<<<cdiv((long)128 * DI, 256), 256>>>(
            Wx + (size_t)l * XDBLW * DI, XDBLW, 128, DI, DI,
            swx + (size_t)l * 128 * 2 * DI);
    split2_kernel<<<cdiv((long)DEPTH * DI * DTRANK, 256), 256>>>(
        Wdt, DEPTH * DI, DEPTH * DI, DTRANK, DTRANK, swdt);
    split2_kernel<<<cdiv((long)DEPTH * DDIM * DI, 256), 256>>>(
        Wo, DEPTH * DDIM, DEPTH * DDIM, DI, DI, swo);

    // ---- layer-0 input split ---------------------------------------------
    split2_kernel<<<cdiv((long)ROWS * DDIM, 256), 256>>>(
        x0, ROWS, ROWS, DDIM, DDIM, sa);

    for (int l = 0; l < DEPTH; l++) {
        // in_proj: sa [4096,2x1024] x swi -> xz [4096,4096]
        bf16_gemm_kernel<128, 2, 4, 4><<<dim3(XZW / 128, ROWS / 128), 256>>>(
            sa, swi + (size_t)l * XZW * 2 * DDIM, xz, XZW, XZW, DDIM,
            0, nullptr, nullptr);

        // conv + silu -> xs fp32 + xs-split (into sa)
        conv_silu_kernel<<<(ROWS * DI) / 256, 256>>>(
            xz, cw + (size_t)l * DI * DCONV, cb + (size_t)l * DI, xs, sa);

        // x_proj (TM=32 for SM fill): -> xdbl fp32, emits dt split into sdt
        bf16_gemm_kernel<32, 1, 2, 2><<<dim3(1, ROWS / 32), 256>>>(
            sa, swx + (size_t)l * 128 * 2 * DI, xdbl, XDBLW, XDBLW, DI,
            0, nullptr, sdt);

        // dt_proj + softplus: sdt x swdt -> delta
        bf16_gemm_kernel<128, 2, 4, 4><<<dim3(DI / 128, ROWS / 128), 256>>>(
            sdt, swdt + (size_t)l * DI * 2 * DTRANK, delta, DI, DI, DTRANK,
            1, bdt + (size_t)l * DI, nullptr);

        // scan + D skip + gate -> y-split (into sa)
        scan_kernel<<<(BB * DI) / 8, 128>>>(
            xs, delta, xdbl, Alog + (size_t)l * DI * NSTATE,
            Dp + (size_t)l * DI, xz, sa);

        // out_proj: sa x swo -> xz [4096,1024]
        bf16_gemm_kernel<128, 2, 4, 4><<<dim3(DDIM / 128, ROWS / 128), 256>>>(
            sa, swo + (size_t)l * DDIM * 2 * DI, xz, DDIM, DDIM, DI,
            0, nullptr, nullptr);

        // rmsnorm -> next-layer split (into sa) or final fp32 output
        if (l == DEPTH - 1)
            rmsnorm_kernel<<<ROWS, 256>>>(xz, rw + (size_t)l * DDIM,
                                          (float*)d_out, nullptr);
        else
            rmsnorm_kernel<<<ROWS, 256>>>(xz, rw + (size_t)l * DDIM,
                                          nullptr, sa);
    }
}

// round 17
// speedup vs baseline: 1.9152x; 1.9152x over previous
#include <cuda_runtime.h>
#include <cuda_bf16.h>
#include <math.h>
#include <stdint.h>

#define DEPTH  8
#define DDIM   1024
#define DI     2048
#define NSTATE 16
#define DCONV  4
#define DTRANK 64
#define BB     2
#define LLEN   2048
#define ROWS   (BB*LLEN)           // 4096
#define XZW    (2*DI)              // 4096
#define XDBLW  (DTRANK + 2*NSTATE) // 96

// ---------------- scratch (static device globals; no allocation) ----------
__device__ float g_xz   [(size_t)ROWS * XZW];
__device__ float g_xs   [(size_t)ROWS * DI];
__device__ float g_xdbl [(size_t)ROWS * XDBLW];
__device__ float g_delta[(size_t)ROWS * DI];
__device__ float g_y    [(size_t)ROWS * DI];
__device__ float g_x    [(size_t)ROWS * DDIM];
__device__ __nv_bfloat16 g_sa  [(size_t)ROWS * 2 * DI];            // activation split
__device__ __nv_bfloat16 g_sdt [(size_t)ROWS * 2 * DTRANK];        // dt split
__device__ __nv_bfloat16 g_swi [(size_t)DEPTH * XZW * 2 * DDIM];   // Wi split
__device__ __nv_bfloat16 g_swx [(size_t)DEPTH * 128 * 2 * DI];     // Wx split (rows padded)
__device__ __nv_bfloat16 g_swdt[(size_t)DEPTH * DI * 2 * DTRANK];  // Wdt split
__device__ __nv_bfloat16 g_swo [(size_t)DEPTH * DDIM * 2 * DI];    // Wo split

// ======================= helpers ==========================================
__device__ __forceinline__ uint32_t s2u(const void* p) {
    uint32_t a;
    asm("{ .reg .u64 t; cvta.to.shared.u64 t, %1; cvt.u32.u64 %0, t; }"
        : "=r"(a) : "l"(p));
    return a;
}
#define CP16(dst, src) \
    asm volatile("cp.async.cg.shared.global [%0], [%1], 16;" :: "r"(dst), "l"(src))
#define CP_COMMIT()  asm volatile("cp.async.commit_group;" ::: "memory")
#define CP_WAIT0()   asm volatile("cp.async.wait_group 0;" ::: "memory")

__device__ __forceinline__ void mma16816(float* c, uint32_t a0, uint32_t a1,
                                         uint32_t a2, uint32_t a3,
                                         uint32_t b0, uint32_t b1) {
    asm volatile(
        "mma.sync.aligned.m16n8k16.row.col.f32.bf16.bf16.f32 "
        "{%0,%1,%2,%3}, {%4,%5,%6,%7}, {%8,%9}, {%0,%1,%2,%3};"
        : "+f"(c[0]), "+f"(c[1]), "+f"(c[2]), "+f"(c[3])
        : "r"(a0), "r"(a1), "r"(a2), "r"(a3), "r"(b0), "r"(b1));
}

// ======================= bf16 2-way split =================================
// out[r, 0:K)=h, [K:2K)=l; rows >= R zeroed.
__global__ __launch_bounds__(256) void split2_kernel(
    const float* __restrict__ X, int R, int Rpad, int K, int ldx,
    __nv_bfloat16* __restrict__ out)
{
    long i = (long)blockIdx.x * blockDim.x + threadIdx.x;
    if (i >= (long)Rpad * K) return;
    int k = (int)(i % K);
    long r = i / K;
    float x = (r < R) ? X[r * (long)ldx + k] : 0.f;
    __nv_bfloat16 h = __float2bfloat16(x);
    __nv_bfloat16 l = __float2bfloat16(x - __bfloat162float(h));
    __nv_bfloat16* o = out + r * (long)(2 * K);
    o[k] = h; o[K + k] = l;
}

// ======================= bf16 GEMM, 3 segments, chunk-spill (R15) =========
// C[M,N] = {hh + lh + hl} of A_seg[M,K] * W_seg[N,K]^T; A,W: [rows, 2K]=[h|l].
// 128x128 CTA tile, BK=32, 256 threads, warps 2(M)x4(N), m16n8k16.
#define BKC   32
#define SSTR  40
#define SEGA_PACK 0x010u   // A segments per pass: 0,1,0
#define SEGB_PACK 0x100u   // B segments per pass: 0,0,1

__global__ __launch_bounds__(256) void bf16_gemm_kernel(
    const __nv_bfloat16* __restrict__ A,
    const __nv_bfloat16* __restrict__ W,
    float* __restrict__ C, int ldc,
    int Ntrue, int K,
    int do_sp, const float* __restrict__ bias)
{
    __shared__ __nv_bfloat16 sA[2][128 * SSTR];
    __shared__ __nv_bfloat16 sB[2][128 * SSTR];

    const int tid = threadIdx.x;
    const int m0 = blockIdx.y * 128;
    const int n0 = blockIdx.x * 128;

    const int ldrow = tid >> 1;
    const int ldoff = (tid & 1) * 32;
    const char* gA = (const char*)(A + (size_t)(m0 + ldrow) * (2 * K)) + ldoff;
    const char* gB = (const char*)(W + (size_t)(n0 + ldrow) * (2 * K)) + ldoff;
    const uint32_t dA[2] = { s2u(&sA[0][0]) + ldrow * (SSTR * 2) + ldoff,
                             s2u(&sA[1][0]) + ldrow * (SSTR * 2) + ldoff };
    const uint32_t dB[2] = { s2u(&sB[0][0]) + ldrow * (SSTR * 2) + ldoff,
                             s2u(&sB[1][0]) + ldrow * (SSTR * 2) + ldoff };

    const int nkr = K / BKC;
    const int total = 3 * nkr;

    auto load_chunk = [&](int c, int buf) {
        const int p = c / nkr;
        const int kk = c - p * nkr;
        const int sa_off = (int)((SEGA_PACK >> (4 * p)) & 3) * K + kk * BKC;
        const int sb_off = (int)((SEGB_PACK >> (4 * p)) & 3) * K + kk * BKC;
        const char* pa = gA + (size_t)sa_off * 2;
        const char* pb = gB + (size_t)sb_off * 2;
        CP16(dA[buf],      pa);
        CP16(dA[buf] + 16, pa + 16);
        CP16(dB[buf],      pb);
        CP16(dB[buf] + 16, pb + 16);
    };

    const int wid = tid >> 5, lane = tid & 31;
    const int wm = wid & 1;
    const int wn = wid >> 1;
    const int g = lane >> 2, t = lane & 3;

    float accP[4][4][4];
    float acc[4][4][4];
#pragma unroll
    for (int i = 0; i < 4; i++)
#pragma unroll
        for (int j = 0; j < 4; j++)
#pragma unroll
            for (int q = 0; q < 4; q++) { accP[i][j][q] = 0.f; acc[i][j][q] = 0.f; }

    load_chunk(0, 0);
    CP_COMMIT();

    for (int c = 0; c < total; c++) {
        const int buf = c & 1;
        CP_WAIT0();
        __syncthreads();
        if (c + 1 < total) {
            load_chunk(c + 1, buf ^ 1);
            CP_COMMIT();
        }

        const __nv_bfloat16* pA = &sA[buf][0];
        const __nv_bfloat16* pB = &sB[buf][0];
#pragma unroll
        for (int ks = 0; ks < 2; ks++) {
            const int kb = ks * 16 + t * 2;
            uint32_t af[4][4], bf[4][2];
#pragma unroll
            for (int mt = 0; mt < 4; mt++) {
                const int r = wm * 64 + mt * 16 + g;
                af[mt][0] = *(const uint32_t*)&pA[r * SSTR + kb];
                af[mt][1] = *(const uint32_t*)&pA[(r + 8) * SSTR + kb];
                af[mt][2] = *(const uint32_t*)&pA[r * SSTR + kb + 8];
                af[mt][3] = *(const uint32_t*)&pA[(r + 8) * SSTR + kb + 8];
            }
#pragma unroll
            for (int nt = 0; nt < 4; nt++) {
                const int cc = wn * 32 + nt * 8 + g;
                bf[nt][0] = *(const uint32_t*)&pB[cc * SSTR + kb];
                bf[nt][1] = *(const uint32_t*)&pB[cc * SSTR + kb + 8];
            }
#pragma unroll
            for (int mt = 0; mt < 4; mt++)
#pragma unroll
                for (int nt = 0; nt < 4; nt++)
                    mma16816(acc[mt][nt], af[mt][0], af[mt][1], af[mt][2],
                             af[mt][3], bf[nt][0], bf[nt][1]);
        }
#pragma unroll
        for (int mt = 0; mt < 4; mt++)
#pragma unroll
            for (int nt = 0; nt < 4; nt++)
#pragma unroll
                for (int q = 0; q < 4; q++) {
                    accP[mt][nt][q] += acc[mt][nt][q];
                    acc[mt][nt][q] = 0.f;
                }
    }

#pragma unroll
    for (int mt = 0; mt < 4; mt++) {
        const int r0 = m0 + wm * 64 + mt * 16 + g;
#pragma unroll
        for (int nt = 0; nt < 4; nt++) {
            const int cc = n0 + wn * 32 + nt * 8 + t * 2;
            if (cc >= Ntrue) continue;
            float v0 = accP[mt][nt][0], v1 = accP[mt][nt][1];
            float v2 = accP[mt][nt][2], v3 = accP[mt][nt][3];
            if (do_sp) {
                const float b0 = bias[cc], b1 = bias[cc + 1];
                v0 += b0; v1 += b1; v2 += b0; v3 += b1;
                v0 = fmaxf(v0, 0.f) + log1pf(expf(-fabsf(v0)));
                v1 = fmaxf(v1, 0.f) + log1pf(expf(-fabsf(v1)));
                v2 = fmaxf(v2, 0.f) + log1pf(expf(-fabsf(v2)));
                v3 = fmaxf(v3, 0.f) + log1pf(expf(-fabsf(v3)));
            }
            *(float2*)(C + (size_t)r0 * ldc + cc)       = make_float2(v0, v1);
            *(float2*)(C + (size_t)(r0 + 8) * ldc + cc) = make_float2(v2, v3);
        }
    }
}

// ======================= x_proj GEMM: 32x128 tile (SM fill) ===============
// Standalone small-M variant; 8 warps 1(M)x8(N), warp tile 32x16, MT=NT=2.
__global__ __launch_bounds__(256) void xproj_gemm_kernel(
    const __nv_bfloat16* __restrict__ A,
    const __nv_bfloat16* __restrict__ W,
    float* __restrict__ C, int ldc,
    int Ntrue, int K)
{
    __shared__ __nv_bfloat16 sA[2][32 * SSTR];
    __shared__ __nv_bfloat16 sB[2][128 * SSTR];

    const int tid = threadIdx.x;
    const int m0 = blockIdx.y * 32;

    const int ldrowB = tid >> 1, ldoffB = (tid & 1) * 32;
    const char* gB = (const char*)(W + (size_t)ldrowB * (2 * K)) + ldoffB;
    const uint32_t dB[2] = { s2u(&sB[0][0]) + ldrowB * (SSTR * 2) + ldoffB,
                             s2u(&sB[1][0]) + ldrowB * (SSTR * 2) + ldoffB };
    const int ldrowA = tid >> 2, ldoffA = (tid & 3) * 16;
    const char* gA = (const char*)(A + (size_t)(m0 + ldrowA) * (2 * K)) + ldoffA;
    const uint32_t dA[2] = { s2u(&sA[0][0]) + ldrowA * (SSTR * 2) + ldoffA,
                             s2u(&sA[1][0]) + ldrowA * (SSTR * 2) + ldoffA };

    const int nkr = K / BKC;
    const int total = 3 * nkr;

    auto load_chunk = [&](int c, int buf) {
        const int p = c / nkr;
        const int kk = c - p * nkr;
        const int sa_off = (int)((SEGA_PACK >> (4 * p)) & 3) * K + kk * BKC;
        const int sb_off = (int)((SEGB_PACK >> (4 * p)) & 3) * K + kk * BKC;
        const char* pb = gB + (size_t)sb_off * 2;
        CP16(dB[buf],      pb);
        CP16(dB[buf] + 16, pb + 16);
        if (tid < 128) {
            const char* pa = gA + (size_t)sa_off * 2;
            CP16(dA[buf], pa);
        }
    };

    const int wid = tid >> 5, lane = tid & 31;
    const int g = lane >> 2, t = lane & 3;

    float accP[2][2][4];
    float acc[2][2][4];
#pragma unroll
    for (int i = 0; i < 2; i++)
#pragma unroll
        for (int j = 0; j < 2; j++)
#pragma unroll
            for (int q = 0; q < 4; q++) { accP[i][j][q] = 0.f; acc[i][j][q] = 0.f; }

    load_chunk(0, 0);
    CP_COMMIT();

    for (int c = 0; c < total; c++) {
        const int buf = c & 1;
        CP_WAIT0();
        __syncthreads();
        if (c + 1 < total) {
            load_chunk(c + 1, buf ^ 1);
            CP_COMMIT();
        }

        const __nv_bfloat16* pA = &sA[buf][0];
        const __nv_bfloat16* pB = &sB[buf][0];
#pragma unroll
        for (int ks = 0; ks < 2; ks++) {
            const int kb = ks * 16 + t * 2;
            uint32_t af[2][4], bf[2][2];
#pragma unroll
            for (int mt = 0; mt < 2; mt++) {
                const int r = mt * 16 + g;
                af[mt][0] = *(const uint32_t*)&pA[r * SSTR + kb];
                af[mt][1] = *(const uint32_t*)&pA[(r + 8) * SSTR + kb];
                af[mt][2] = *(const uint32_t*)&pA[r * SSTR + kb + 8];
                af[mt][3] = *(const uint32_t*)&pA[(r + 8) * SSTR + kb + 8];
            }
#pragma unroll
            for (int nt = 0; nt < 2; nt++) {
                const int cc = wid * 16 + nt * 8 + g;
                bf[nt][0] = *(const uint32_t*)&pB[cc * SSTR + kb];
                bf[nt][1] = *(const uint32_t*)&pB[cc * SSTR + kb + 8];
            }
#pragma unroll
            for (int mt = 0; mt < 2; mt++)
#pragma unroll
                for (int nt = 0; nt < 2; nt++)
                    mma16816(acc[mt][nt], af[mt][0], af[mt][1], af[mt][2],
                             af[mt][3], bf[nt][0], bf[nt][1]);
        }
#pragma unroll
        for (int mt = 0; mt < 2; mt++)
#pragma unroll
            for (int nt = 0; nt < 2; nt++)
#pragma unroll
                for (int q = 0; q < 4; q++) {
                    accP[mt][nt][q] += acc[mt][nt][q];
                    acc[mt][nt][q] = 0.f;
                }
    }

#pragma unroll
    for (int mt = 0; mt < 2; mt++) {
        const int r0 = m0 + mt * 16 + g;
#pragma unroll
        for (int nt = 0; nt < 2; nt++) {
            const int cc = wid * 16 + nt * 8 + t * 2;
            if (cc >= Ntrue) continue;
            *(float2*)(C + (size_t)r0 * ldc + cc) =
                make_float2(accP[mt][nt][0], accP[mt][nt][1]);
            *(float2*)(C + (size_t)(r0 + 8) * ldc + cc) =
                make_float2(accP[mt][nt][2], accP[mt][nt][3]);
        }
    }
}

// ---------------- depthwise causal conv (width 4) + bias + silu -----------
__global__ __launch_bounds__(256) void conv_silu_kernel(
    const float* __restrict__ xz, const float* __restrict__ cw,
    const float* __restrict__ cb, float* __restrict__ xs)
{
    const int i = blockIdx.x * blockDim.x + threadIdx.x;
    if (i >= ROWS * DI) return;
    const int d = i & (DI - 1);
    const int r = i >> 11;
    const int t = r & (LLEN - 1);
    float acc = cb[d];
    const float* base = xz + (size_t)r * XZW + d;
#pragma unroll
    for (int j = 0; j < DCONV; j++) {
        const int tt = t - (DCONV - 1) + j;
        if (tt >= 0)
            acc += cw[d * DCONV + j] * base[(long)(tt - t) * XZW];
    }
    xs[i] = acc / (1.f + __expf(-acc));
}

// ---------------- selective scan: 16 lanes per (b,d) channel --------------
__global__ __launch_bounds__(128) void scan_kernel(
    const float* __restrict__ xs, const float* __restrict__ delta,
    const float* __restrict__ xdbl, const float* __restrict__ A_log,
    const float* __restrict__ Dp, float* __restrict__ y)
{
    const int lane = threadIdx.x & 15;
    const int ch = blockIdx.x * (blockDim.x >> 4) + (threadIdx.x >> 4);
    const int b = ch / DI, d = ch & (DI - 1);
    const float A  = -expf(A_log[d * NSTATE + lane]);
    const float Dd = Dp[d];

    const float* xsP = xs    + (size_t)b * LLEN * DI + d;
    const float* dlP = delta + (size_t)b * LLEN * DI + d;
    const float* bcP = xdbl  + (size_t)b * LLEN * XDBLW + DTRANK + lane;
    float*       yP  = y     + (size_t)b * LLEN * DI + d;

    float h = 0.f;
    for (int t = 0; t < LLEN; t++) {
        const float dt = dlP[0];
        const float xt = xsP[0];
        const float Bt = bcP[0];
        const float Ct = bcP[NSTATE];
        const float dA = __expf(dt * A);
        h = dA * h + (dt * xt) * Bt;
        float p = h * Ct;
        p += __shfl_xor_sync(0xffffffffu, p, 1);
        p += __shfl_xor_sync(0xffffffffu, p, 2);
        p += __shfl_xor_sync(0xffffffffu, p, 4);
        p += __shfl_xor_sync(0xffffffffu, p, 8);
        if (lane == 0) yP[0] = p + Dd * xt;
        xsP += DI; dlP += DI; bcP += XDBLW; yP += DI;
    }
}

// ---------------- gate: y *= silu(z) --------------------------------------
__global__ __launch_bounds__(256) void gate_kernel(
    float* __restrict__ y, const float* __restrict__ xz)
{
    const int i = blockIdx.x * blockDim.x + threadIdx.x;
    if (i >= ROWS * DI) return;
    const int d = i & (DI - 1);
    const int r = i >> 11;
    const float z = xz[(size_t)r * XZW + DI + d];
    y[i] *= z / (1.f + __expf(-z));
}

// ---------------- rmsnorm per row -----------------------------------------
__global__ __launch_bounds__(256) void rmsnorm_kernel(
    const float* __restrict__ in, const float* __restrict__ w,
    float* __restrict__ out)
{
    const int r = blockIdx.x;
    const int tid = threadIdx.x;
    const float* row = in + (size_t)r * DDIM;
    float v[4];
    float ss = 0.f;
#pragma unroll
    for (int j = 0; j < 4; j++) {
        v[j] = row[tid + j * 256];
        ss += v[j] * v[j];
    }
#pragma unroll
    for (int o = 16; o > 0; o >>= 1) ss += __shfl_xor_sync(0xffffffffu, ss, o);
    __shared__ float ws[8];
    if ((tid & 31) == 0) ws[tid >> 5] = ss;
    __syncthreads();
    float tot = 0.f;
#pragma unroll
    for (int k = 0; k < 8; k++) tot += ws[k];
    const float inv = rsqrtf(tot * (1.f / (float)DDIM) + 1e-5f);
#pragma unroll
    for (int j = 0; j < 4; j++)
        out[(size_t)r * DDIM + tid + j * 256] = v[j] * inv * w[tid + j * 256];
}

// ---------------- host launch ---------------------------------------------
static inline int cdiv(long a, int b) { return (int)((a + b - 1) / b); }

extern "C" void kernel_launch(void* const* d_in, const int* in_sizes, int n_in,
                              void* d_out, int out_size)
{
    const float* x0   = (const float*)d_in[0];
    const float* Wi   = (const float*)d_in[1];   // [8, 4096, 1024]
    const float* cw   = (const float*)d_in[2];   // [8, 2048, 4]
    const float* cb   = (const float*)d_in[3];   // [8, 2048]
    const float* Wx   = (const float*)d_in[4];   // [8, 96, 2048]
    const float* Wdt  = (const float*)d_in[5];   // [8, 2048, 64]
    const float* bdt  = (const float*)d_in[6];   // [8, 2048]
    const float* Alog = (const float*)d_in[7];   // [8, 2048, 16]
    const float* Dp   = (const float*)d_in[8];   // [8, 2048]
    const float* Wo   = (const float*)d_in[9];   // [8, 1024, 2048]
    const float* rw   = (const float*)d_in[10];  // [8, 1024]

    float *xz, *xs, *xdbl, *delta, *y, *xb;
    __nv_bfloat16 *sa, *sdt, *swi, *swx, *swdt, *swo;
    cudaGetSymbolAddress((void**)&xz,    g_xz);
    cudaGetSymbolAddress((void**)&xs,    g_xs);
    cudaGetSymbolAddress((void**)&xdbl,  g_xdbl);
    cudaGetSymbolAddress((void**)&delta, g_delta);
    cudaGetSymbolAddress((void**)&y,     g_y);
    cudaGetSymbolAddress((void**)&xb,    g_x);
    cudaGetSymbolAddress((void**)&sa,    g_sa);
    cudaGetSymbolAddress((void**)&sdt,   g_sdt);
    cudaGetSymbolAddress((void**)&swi,   g_swi);
    cudaGetSymbolAddress((void**)&swx,   g_swx);
    cudaGetSymbolAddress((void**)&swdt,  g_swdt);
    cudaGetSymbolAddress((void**)&swo,   g_swo);

    // ---- weight splits once, up-front ------------------------------------
    split2_kernel<<<cdiv((long)DEPTH * XZW * DDIM, 256), 256>>>(
        Wi, DEPTH * XZW, DEPTH * XZW, DDIM, DDIM, swi);
    for (int l = 0; l < DEPTH; l++)
        split2_kernel<<<cdiv((long)128 * DI, 256), 256>>>(
            Wx + (size_t)l * XDBLW * DI, XDBLW, 128, DI, DI,
            swx + (size_t)l * 128 * 2 * DI);
    split2_kernel<<<cdiv((long)DEPTH * DI * DTRANK, 256), 256>>>(
        Wdt, DEPTH * DI, DEPTH * DI, DTRANK, DTRANK, swdt);
    split2_kernel<<<cdiv((long)DEPTH * DDIM * DI, 256), 256>>>(
        Wo, DEPTH * DDIM, DEPTH * DDIM, DI, DI, swo);

    const float* xin = x0;
    for (int l = 0; l < DEPTH; l++) {
        // in_proj
        split2_kernel<<<cdiv((long)ROWS * DDIM, 256), 256>>>(
            xin, ROWS, ROWS, DDIM, DDIM, sa);
        bf16_gemm_kernel<<<dim3(XZW / 128, ROWS / 128), 256>>>(
            sa, swi + (size_t)l * XZW * 2 * DDIM, xz, XZW, XZW, DDIM,
            0, nullptr);

        // conv + silu
        conv_silu_kernel<<<(ROWS * DI) / 256, 256>>>(
            xz, cw + (size_t)l * DI * DCONV, cb + (size_t)l * DI, xs);

        // x_proj (TM=32 standalone kernel: 128 CTAs)
        split2_kernel<<<cdiv((long)ROWS * DI, 256), 256>>>(
            xs, ROWS, ROWS, DI, DI, sa);
        xproj_gemm_kernel<<<dim3(1, ROWS / 32), 256>>>(
            sa, swx + (size_t)l * 128 * 2 * DI, xdbl, XDBLW, XDBLW, DI);

        // dt_proj + softplus
        split2_kernel<<<cdiv((long)ROWS * DTRANK, 256), 256>>>(
            xdbl, ROWS, ROWS, DTRANK, XDBLW, sdt);
        bf16_gemm_kernel<<<dim3(DI / 128, ROWS / 128), 256>>>(
            sdt, swdt + (size_t)l * DI * 2 * DTRANK, delta, DI, DI, DTRANK,
            1, bdt + (size_t)l * DI);

        // scan + gate
        scan_kernel<<<(BB * DI) / 8, 128>>>(
            xs, delta, xdbl, Alog + (size_t)l * DI * NSTATE,
            Dp + (size_t)l * DI, y);
        gate_kernel<<<(ROWS * DI) / 256, 256>>>(y, xz);

        // out_proj
        split2_kernel<<<cdiv((long)ROWS * DI, 256), 256>>>(
            y, ROWS, ROWS, DI, DI, sa);
        bf16_gemm_kernel<<<dim3(DDIM / 128, ROWS / 128), 256>>>(
            sa, swo + (size_t)l * DDIM * 2 * DI, xz, DDIM, DDIM, DI,
            0, nullptr);

        // rmsnorm
        float* outp = (l == DEPTH - 1) ? (float*)d_out : xb;
        rmsnorm_kernel<<<ROWS, 256>>>(xz, rw + (size_t)l * DDIM, outp);
        xin = xb;
    }
}